// round 10
// baseline (speedup 1.0000x reference)
#include <cuda_runtime.h>
#include <cstdint>

// BKT 2-state HMM forward-backward, 128-way time-segmented matrix scan.
// corr: (B,T) int32 ; dynamics_logits: (B,3) f32 ; obs_logits: (B,T,2) f32
// out: (3,B,T,2) f32 = [output_logprobs, state_posteriors, smoothed]
// All scratch arrays row-major -> every K3 block touches only contiguous spans.

#define BN   8192
#define TT   1024
#define SEG  128
#define L    8
#define LN2F 0.69314718055994531f

__device__ float4 g_P4[SEG * BN];   // row-major [row*SEG+seg]: raw segment 2x2 products
__device__ float4 g_ab[SEG * BN];   // row-major [row*SEG+seg]: (a0,a1,C,-) at segment start
__device__ float2 g_bb[SEG * BN];   // row-major [row*SEG+seg]: (b0,b1) at segment end

// fast hardware reciprocal (single MUFU.RCP, ~16cyc, rel err ~2^-23)
__device__ __forceinline__ float frcp(float x) {
    float r;
    asm("rcp.approx.f32 %0, %1;" : "=f"(r) : "f"(x));
    return r;
}

__device__ __forceinline__ void trans_from_dyn(const float* __restrict__ dyn, int row,
                                               float& t00, float& t10, float& t01, float& t11)
{
    float d0 = dyn[row * 3 + 0];
    float d1 = dyn[row * 3 + 1];
    float e0 = __expf(d0), e1 = __expf(d1);
    float r0 = frcp(1.f + e0);
    float r1 = frcp(1.f + e1);
    t00 = r0;      t10 = e0 * r0;   // src=0 column (sums to 1)
    t01 = e1 * r1; t11 = r1;        // src=1 column (sums to 1)
}

// ---------------- K1: per-segment 2x2 matrix products (contiguous per block) ----------------
__global__ __launch_bounds__(256)
void k1_products(const int* __restrict__ corr,
                 const float* __restrict__ dyn,
                 const float* __restrict__ obs)
{
    const int tid = threadIdx.x;
    const int row = blockIdx.x * 2 + (tid >> 7);   // 2 rows per block
    const int seg = tid & 127;

    float o[2 * L];
    const float4* op = (const float4*)(obs + (size_t)row * (TT * 2) + seg * (2 * L));
#pragma unroll
    for (int i = 0; i < 4; i++) {
        float4 v = op[i];
        o[4 * i + 0] = v.x; o[4 * i + 1] = v.y;
        o[4 * i + 2] = v.z; o[4 * i + 3] = v.w;
    }
    int yb[L];
    const int4* cp = (const int4*)(corr + (size_t)row * TT + seg * L);
#pragma unroll
    for (int i = 0; i < 2; i++) {
        int4 v = cp[i];
        yb[4 * i + 0] = v.x; yb[4 * i + 1] = v.y;
        yb[4 * i + 2] = v.z; yb[4 * i + 3] = v.w;
    }

    float t00, t10, t01, t11;
    trans_from_dyn(dyn, row, t00, t10, t01, t11);

    float A00 = 1.f, A01 = 0.f, A10 = 0.f, A11 = 1.f;
#pragma unroll
    for (int j = 0; j < L; j++) {
        float e0 = __expf(o[2 * j]), e1 = __expf(o[2 * j + 1]);
        float r0 = frcp(1.f + e0);
        float r1 = frcp(1.f + e1);
        float py0 = yb[j] ? e0 * r0 : r0;
        float py1 = yb[j] ? r1 : e1 * r1;

        float m00 = t00 * py0, m01 = t01 * py1;
        float m10 = t10 * py0, m11 = t11 * py1;
        float n00 = m00 * A00 + m01 * A10;
        float n01 = m00 * A01 + m01 * A11;
        float n10 = m10 * A00 + m11 * A10;
        float n11 = m10 * A01 + m11 * A11;
        A00 = n00; A01 = n01; A10 = n10; A11 = n11;
    }
    g_P4[row * SEG + seg] = make_float4(A00, A01, A10, A11);   // coalesced contiguous
}

// ---------------- K2: boundary scan over segments (alpha & beta interleaved) ----------------
__global__ __launch_bounds__(64)
void k2_scan(const float* __restrict__ dyn)
{
    const int row = blockIdx.x * 64 + threadIdx.x;

    float d2 = dyn[row * 3 + 2];
    float ed2 = __expf(d2);
    float ri2 = frcp(1.f + ed2);
    float a0 = ri2, a1 = ed2 * ri2;
    int Ea = 0;
    float b0 = 1.f, b1 = 1.f;

#pragma unroll 8
    for (int k = 0; k < SEG; k++) {
        float s  = a0 + a1;
        float rs = frcp(s);
        float C  = (float)Ea * LN2F + __logf(s);
        g_ab[row * SEG + k] = make_float4(a0 * rs, a1 * rs, C, 0.f);  // lane-local 128B runs

        float4 P = g_P4[row * SEG + k];
        float na0 = P.x * a0 + P.y * a1;
        float na1 = P.z * a0 + P.w * a1;
        float ss = na0 + na1;
        int eb = (__float_as_int(ss) >> 23) & 0xFF;
        float sca = __int_as_float((254 - eb) << 23);
        a0 = na0 * sca; a1 = na1 * sca;
        Ea += eb - 127;

        int kb = SEG - 1 - k;
        g_bb[row * SEG + kb] = make_float2(b0, b1);
        if (kb > 0) {
            float4 Pb = g_P4[row * SEG + kb];
            float nb0 = Pb.x * b0 + Pb.z * b1;   // P^T * b
            float nb1 = Pb.y * b0 + Pb.w * b1;
            float sb = nb0 + nb1;
            int ebb = (__float_as_int(sb) >> 23) & 0xFF;
            float scb = __int_as_float((254 - ebb) << 23);
            b0 = nb0 * scb; b1 = nb1 * scb;
        }
    }
}

// ---------------- K3: per-segment outputs (2 rows/block, coalesced scratch reads) ----------------
__global__ __launch_bounds__(256, 3)
void k3_outputs(const int* __restrict__ corr,
                const float* __restrict__ dyn,
                const float* __restrict__ obs,
                float* __restrict__ out)
{
    const int tid = threadIdx.x;
    const int row = blockIdx.x * 2 + (tid >> 7);   // 2 rows per block
    const int seg = tid & 127;

    float o[2 * L];
    const float4* op = (const float4*)(obs + (size_t)row * (TT * 2) + seg * (2 * L));
#pragma unroll
    for (int i = 0; i < 4; i++) {
        float4 v = op[i];
        o[4 * i + 0] = v.x; o[4 * i + 1] = v.y;
        o[4 * i + 2] = v.z; o[4 * i + 3] = v.w;
    }
    unsigned ymask = 0;
    const int4* cp = (const int4*)(corr + (size_t)row * TT + seg * L);
#pragma unroll
    for (int i = 0; i < 2; i++) {
        int4 v = cp[i];
        ymask |= (unsigned)(v.x & 1) << (4 * i + 0);
        ymask |= (unsigned)(v.y & 1) << (4 * i + 1);
        ymask |= (unsigned)(v.z & 1) << (4 * i + 2);
        ymask |= (unsigned)(v.w & 1) << (4 * i + 3);
    }

    float t00, t10, t01, t11;
    trans_from_dyn(dyn, row, t00, t10, t01, t11);

    const int gi = row * SEG + seg;       // row-major: warp reads contiguous 512B
    float4 ab = g_ab[gi];
    float a0 = ab.x, a1 = ab.y, C = ab.z;

    float4* predP = (float4*)(out + (size_t)row * (TT * 2) + seg * (2 * L));
    float4* postP = (float4*)(out + (size_t)BN * TT * 2 + (size_t)row * (TT * 2) + seg * (2 * L));
    float4* smP   = (float4*)(out + (size_t)2 * BN * TT * 2 + (size_t)row * (TT * 2) + seg * (2 * L));

    // ---- forward sub-walk: pred + post + f0; o[] replaced in place by emissions ----
    float f0s[L];
    float pr0 = 0.f, pr1 = 0.f, po0 = 0.f, po1 = 0.f;
#pragma unroll
    for (int j = 0; j < L; j++) {
        int y = (ymask >> j) & 1;
        float e0 = __expf(o[2 * j]), e1 = __expf(o[2 * j + 1]);
        float r0 = frcp(1.f + e0);
        float r1 = frcp(1.f + e1);
        float py0 = y ? e0 * r0 : r0;
        float py1 = y ? r1 : e1 * r1;
        o[2 * j]     = py0;              // reuse registers: logits -> emissions
        o[2 * j + 1] = py1;

        float jj0 = a0 * py0;
        float jj1 = a1 * py1;
        float js  = jj0 + jj1;           // predictive prob of observed symbol
        float ljs = __logf(js);
        float lns = __logf(1.f - js);    // predictive probs sum to 1 (a normalized)
        float lp0 = y ? lns : ljs;
        float lp1 = y ? ljs : lns;
        float post0 = __logf(jj0) + C;
        float post1 = __logf(jj1) + C;

        float f  = jj0 * frcp(js);
        f0s[j] = f;
        float fc = 1.f - f;
        a0 = t00 * f + t01 * fc;         // stays normalized (T columns sum to 1)
        a1 = t10 * f + t11 * fc;
        C += ljs;

        if ((j & 1) == 0) {
            pr0 = lp0; pr1 = lp1; po0 = post0; po1 = post1;
        } else {
            predP[j >> 1] = make_float4(pr0, pr1, lp0, lp1);
            postP[j >> 1] = make_float4(po0, po1, post0, post1);
        }
    }

    // ---- backward sub-walk: smoothed (descending; store pairs) ----
    float2 bb = g_bb[gi];
    float b0 = bb.x, b1 = bb.y;
    float sh0 = 0.f, sh1 = 0.f;
#pragma unroll
    for (int j = L - 1; j >= 0; j--) {
        float f  = f0s[j];
        float fc = 1.f - f;
        float g0 = f  * b0;
        float g1 = fc * b1;
        float rg = frcp(g0 + g1);
        float s0 = __logf(g0 * rg);
        float s1 = __logf(g1 * rg);

        if (j & 1) {
            sh0 = s0; sh1 = s1;
        } else {
            smP[j >> 1] = make_float4(s0, s1, sh0, sh1);
        }

        // beta update to t-1 (no in-segment rescale needed: >= ~1e-24)
        float u0 = o[2 * j]     * b0;
        float u1 = o[2 * j + 1] * b1;
        b0 = t00 * u0 + t10 * u1;
        b1 = t01 * u0 + t11 * u1;
    }
}

extern "C" void kernel_launch(void* const* d_in, const int* in_sizes, int n_in,
                              void* d_out, int out_size)
{
    const int*   corr = (const int*)d_in[0];
    const float* dyn  = (const float*)d_in[1];
    const float* obs  = (const float*)d_in[2];
    float* out = (float*)d_out;

    k1_products<<<BN / 2, 256>>>(corr, dyn, obs);
    k2_scan<<<BN / 64, 64>>>(dyn);
    k3_outputs<<<BN / 2, 256>>>(corr, dyn, obs, out);
}

// round 11
// speedup vs baseline: 1.0637x; 1.0637x over previous
#include <cuda_runtime.h>
#include <cstdint>

// BKT 2-state HMM forward-backward, 128-way time-segmented matrix scan.
// corr: (B,T) int32 ; dynamics_logits: (B,3) f32 ; obs_logits: (B,T,2) f32
// out: (3,B,T,2) f32 = [output_logprobs, state_posteriors, smoothed]

#define BN   8192
#define TT   1024
#define SEG  128
#define L    8
#define LN2F 0.69314718055994531f

__device__ float4 g_P4[SEG * BN];   // row-major [row*SEG+seg]: raw segment 2x2 products
__device__ float4 g_ab[SEG * BN];   // row-major [row*SEG+seg]: (a0,a1,C,-) at segment start
__device__ float2 g_bb[SEG * BN];   // row-major [row*SEG+seg]: (b0,b1) at segment end

// fast hardware reciprocal (single MUFU.RCP, ~16cyc, rel err ~2^-23)
__device__ __forceinline__ float frcp(float x) {
    float r;
    asm("rcp.approx.f32 %0, %1;" : "=f"(r) : "f"(x));
    return r;
}

__device__ __forceinline__ void trans_from_dyn(const float* __restrict__ dyn, int row,
                                               float& t00, float& t10, float& t01, float& t11)
{
    float d0 = dyn[row * 3 + 0];
    float d1 = dyn[row * 3 + 1];
    float e0 = __expf(d0), e1 = __expf(d1);
    float r0 = frcp(1.f + e0);
    float r1 = frcp(1.f + e1);
    t00 = r0;      t10 = e0 * r0;   // src=0 column (sums to 1)
    t01 = e1 * r1; t11 = r1;        // src=1 column (sums to 1)
}

// ---------------- K1: per-segment 2x2 matrix products (contiguous per block) ----------------
__global__ __launch_bounds__(256)
void k1_products(const int* __restrict__ corr,
                 const float* __restrict__ dyn,
                 const float* __restrict__ obs)
{
    const int tid = threadIdx.x;
    const int row = blockIdx.x * 2 + (tid >> 7);   // 2 rows per block
    const int seg = tid & 127;

    float o[2 * L];
    const float4* op = (const float4*)(obs + (size_t)row * (TT * 2) + seg * (2 * L));
#pragma unroll
    for (int i = 0; i < 4; i++) {
        float4 v = op[i];
        o[4 * i + 0] = v.x; o[4 * i + 1] = v.y;
        o[4 * i + 2] = v.z; o[4 * i + 3] = v.w;
    }
    int yb[L];
    const int4* cp = (const int4*)(corr + (size_t)row * TT + seg * L);
#pragma unroll
    for (int i = 0; i < 2; i++) {
        int4 v = cp[i];
        yb[4 * i + 0] = v.x; yb[4 * i + 1] = v.y;
        yb[4 * i + 2] = v.z; yb[4 * i + 3] = v.w;
    }

    float t00, t10, t01, t11;
    trans_from_dyn(dyn, row, t00, t10, t01, t11);

    float A00 = 1.f, A01 = 0.f, A10 = 0.f, A11 = 1.f;
#pragma unroll
    for (int j = 0; j < L; j++) {
        float e0 = __expf(o[2 * j]), e1 = __expf(o[2 * j + 1]);
        float r0 = frcp(1.f + e0);
        float r1 = frcp(1.f + e1);
        float py0 = yb[j] ? e0 * r0 : r0;
        float py1 = yb[j] ? r1 : e1 * r1;

        float m00 = t00 * py0, m01 = t01 * py1;
        float m10 = t10 * py0, m11 = t11 * py1;
        float n00 = m00 * A00 + m01 * A10;
        float n01 = m00 * A01 + m01 * A11;
        float n10 = m10 * A00 + m11 * A10;
        float n11 = m10 * A01 + m11 * A11;
        A00 = n00; A01 = n01; A10 = n10; A11 = n11;
    }
    g_P4[row * SEG + seg] = make_float4(A00, A01, A10, A11);   // coalesced contiguous
}

// ---------------- K2: boundary scan over segments (alpha & beta interleaved) ----------------
__global__ __launch_bounds__(64)
void k2_scan(const float* __restrict__ dyn)
{
    const int row = blockIdx.x * 64 + threadIdx.x;

    float d2 = dyn[row * 3 + 2];
    float ed2 = __expf(d2);
    float ri2 = frcp(1.f + ed2);
    float a0 = ri2, a1 = ed2 * ri2;
    int Ea = 0;
    float b0 = 1.f, b1 = 1.f;

#pragma unroll 8
    for (int k = 0; k < SEG; k++) {
        float s  = a0 + a1;
        float rs = frcp(s);
        float C  = (float)Ea * LN2F + __logf(s);
        g_ab[row * SEG + k] = make_float4(a0 * rs, a1 * rs, C, 0.f);

        float4 P = g_P4[row * SEG + k];
        float na0 = P.x * a0 + P.y * a1;
        float na1 = P.z * a0 + P.w * a1;
        float ss = na0 + na1;
        int eb = (__float_as_int(ss) >> 23) & 0xFF;
        float sca = __int_as_float((254 - eb) << 23);
        a0 = na0 * sca; a1 = na1 * sca;
        Ea += eb - 127;

        int kb = SEG - 1 - k;
        g_bb[row * SEG + kb] = make_float2(b0, b1);
        if (kb > 0) {
            float4 Pb = g_P4[row * SEG + kb];
            float nb0 = Pb.x * b0 + Pb.z * b1;   // P^T * b
            float nb1 = Pb.y * b0 + Pb.w * b1;
            float sb = nb0 + nb1;
            int ebb = (__float_as_int(sb) >> 23) & 0xFF;
            float scb = __int_as_float((254 - ebb) << 23);
            b0 = nb0 * scb; b1 = nb1 * scb;
        }
    }
}

// ---------------- K3: per-segment outputs, smem-staged full-sector stores ----------------
#define SSTR 17   // smem stride (16 payload + 1 pad)

__global__ __launch_bounds__(128, 4)
void k3_outputs(const int* __restrict__ corr,
                const float* __restrict__ dyn,
                const float* __restrict__ obs,
                float* __restrict__ out)
{
    __shared__ float sP[128 * SSTR];   // pred
    __shared__ float sQ[128 * SSTR];   // post
    __shared__ float sS[128 * SSTR];   // smoothed

    const int tid = threadIdx.x;
    const int row = blockIdx.x;
    const int seg = tid;

    float o[2 * L];
    const float4* op = (const float4*)(obs + (size_t)row * (TT * 2) + seg * (2 * L));
#pragma unroll
    for (int i = 0; i < 4; i++) {
        float4 v = op[i];
        o[4 * i + 0] = v.x; o[4 * i + 1] = v.y;
        o[4 * i + 2] = v.z; o[4 * i + 3] = v.w;
    }
    unsigned ymask = 0;
    const int4* cp = (const int4*)(corr + (size_t)row * TT + seg * L);
#pragma unroll
    for (int i = 0; i < 2; i++) {
        int4 v = cp[i];
        ymask |= (unsigned)(v.x & 1) << (4 * i + 0);
        ymask |= (unsigned)(v.y & 1) << (4 * i + 1);
        ymask |= (unsigned)(v.z & 1) << (4 * i + 2);
        ymask |= (unsigned)(v.w & 1) << (4 * i + 3);
    }

    float t00, t10, t01, t11;
    trans_from_dyn(dyn, row, t00, t10, t01, t11);

    const int gi = row * SEG + seg;
    float4 ab = g_ab[gi];
    float a0 = ab.x, a1 = ab.y, C = ab.z;

    // ---- forward sub-walk: pred + post + f0; o[] replaced in place by emissions ----
    float f0s[L];
#pragma unroll
    for (int j = 0; j < L; j++) {
        int y = (ymask >> j) & 1;
        float e0 = __expf(o[2 * j]), e1 = __expf(o[2 * j + 1]);
        float r0 = frcp(1.f + e0);
        float r1 = frcp(1.f + e1);
        float py0 = y ? e0 * r0 : r0;
        float py1 = y ? r1 : e1 * r1;
        o[2 * j]     = py0;              // reuse registers: logits -> emissions
        o[2 * j + 1] = py1;

        float jj0 = a0 * py0;
        float jj1 = a1 * py1;
        float js  = jj0 + jj1;           // predictive prob of observed symbol
        float ljs = __logf(js);
        float lns = __logf(1.f - js);    // predictive probs sum to 1 (a normalized)
        sP[seg * SSTR + 2 * j]     = y ? lns : ljs;
        sP[seg * SSTR + 2 * j + 1] = y ? ljs : lns;
        sQ[seg * SSTR + 2 * j]     = __logf(jj0) + C;
        sQ[seg * SSTR + 2 * j + 1] = __logf(jj1) + C;

        float f  = jj0 * frcp(js);
        f0s[j] = f;
        float fc = 1.f - f;
        a0 = t00 * f + t01 * fc;         // stays normalized (T columns sum to 1)
        a1 = t10 * f + t11 * fc;
        C += ljs;
    }

    // ---- backward sub-walk: smoothed ----
    float2 bb = g_bb[gi];
    float b0 = bb.x, b1 = bb.y;
#pragma unroll
    for (int j = L - 1; j >= 0; j--) {
        float f  = f0s[j];
        float fc = 1.f - f;
        float g0 = f  * b0;
        float g1 = fc * b1;
        float rg = frcp(g0 + g1);
        sS[seg * SSTR + 2 * j]     = __logf(g0 * rg);
        sS[seg * SSTR + 2 * j + 1] = __logf(g1 * rg);

        // beta update to t-1 (no in-segment rescale needed: >= ~1e-24)
        float u0 = o[2 * j]     * b0;
        float u1 = o[2 * j + 1] * b1;
        b0 = t00 * u0 + t10 * u1;
        b1 = t01 * u0 + t11 * u1;
    }
    __syncthreads();

    // ---- flush: fully-coalesced full-sector stores (consecutive lanes -> consecutive 16B)
    float* dP = out + (size_t)row * (TT * 2);
    float* dQ = out + (size_t)BN * TT * 2 + (size_t)row * (TT * 2);
    float* dS = out + (size_t)2 * BN * TT * 2 + (size_t)row * (TT * 2);
#pragma unroll
    for (int i = 0; i < 4; i++) {
        int g = i * 512 + tid * 4;            // 0..2047, multiple of 4
        int sidx = (g >> 4) * SSTR + (g & 15); // g&15 in {0,4,8,12}: stays in payload
        *(float4*)(dP + g) = make_float4(sP[sidx], sP[sidx + 1], sP[sidx + 2], sP[sidx + 3]);
        *(float4*)(dQ + g) = make_float4(sQ[sidx], sQ[sidx + 1], sQ[sidx + 2], sQ[sidx + 3]);
        *(float4*)(dS + g) = make_float4(sS[sidx], sS[sidx + 1], sS[sidx + 2], sS[sidx + 3]);
    }
}

extern "C" void kernel_launch(void* const* d_in, const int* in_sizes, int n_in,
                              void* d_out, int out_size)
{
    const int*   corr = (const int*)d_in[0];
    const float* dyn  = (const float*)d_in[1];
    const float* obs  = (const float*)d_in[2];
    float* out = (float*)d_out;

    k1_products<<<BN / 2, 256>>>(corr, dyn, obs);
    k2_scan<<<BN / 64, 64>>>(dyn);
    k3_outputs<<<BN, 128>>>(corr, dyn, obs, out);
}

// round 12
// speedup vs baseline: 1.6612x; 1.5616x over previous
#include <cuda_runtime.h>
#include <cstdint>

// BKT 2-state HMM forward-backward, FULLY FUSED: one block = one row,
// block-local Kogge-Stone scan over 128 time segments of 8 steps each.
// corr: (B,T) int32 ; dynamics_logits: (B,3) f32 ; obs_logits: (B,T,2) f32
// out: (3,B,T,2) f32 = [output_logprobs, state_posteriors, smoothed]

#define BN   8192
#define TT   1024
#define SEG  128
#define L    8
#define LN2F 0.69314718055994531f
#define SSTR 17   // smem staging stride (16 payload + 1 pad)

// fast hardware reciprocal (single MUFU.RCP, rel err ~2^-23)
__device__ __forceinline__ float frcp(float x) {
    float r;
    asm("rcp.approx.f32 %0, %1;" : "=f"(r) : "f"(x));
    return r;
}

// 2x2 matrix multiply, layout: x=m00 y=m01 z=m10 w=m11 ; C = A*B
__device__ __forceinline__ float4 mm2(float4 A, float4 B) {
    return make_float4(A.x * B.x + A.y * B.z,
                       A.x * B.y + A.y * B.w,
                       A.z * B.x + A.w * B.z,
                       A.z * B.y + A.w * B.w);
}

// exact power-of-2 renormalization; accumulates exponent in E
__device__ __forceinline__ void renorm(float4& M, int& E) {
    float s = (M.x + M.y) + (M.z + M.w);
    int eb = (__float_as_int(s) >> 23) & 0xFF;
    float sc = __int_as_float((254 - eb) << 23);
    M.x *= sc; M.y *= sc; M.z *= sc; M.w *= sc;
    E += eb - 127;
}

__global__ __launch_bounds__(128, 5)
void bkt_fused(const int* __restrict__ corr,
               const float* __restrict__ dyn,
               const float* __restrict__ obs,
               float* __restrict__ out)
{
    __shared__ float4 sMa[SEG];  __shared__ int sEa[SEG];   // alpha prefix products
    __shared__ float4 sMb[SEG];  __shared__ int sEb[SEG];   // beta suffix products (transposed)
    __shared__ float sP[128 * SSTR];   // pred staging
    __shared__ float sQ[128 * SSTR];   // post staging
    __shared__ float sS[128 * SSTR];   // smoothed staging

    const int k   = threadIdx.x;       // segment index within row
    const int row = blockIdx.x;

    // ---------------- load own segment (contiguous per warp) ----------------
    float o[2 * L];
    const float4* op = (const float4*)(obs + (size_t)row * (TT * 2) + k * (2 * L));
#pragma unroll
    for (int i = 0; i < 4; i++) {
        float4 v = op[i];
        o[4 * i + 0] = v.x; o[4 * i + 1] = v.y;
        o[4 * i + 2] = v.z; o[4 * i + 3] = v.w;
    }
    unsigned ymask = 0;
    const int4* cp = (const int4*)(corr + (size_t)row * TT + k * L);
#pragma unroll
    for (int i = 0; i < 2; i++) {
        int4 v = cp[i];
        ymask |= (unsigned)(v.x & 1) << (4 * i + 0);
        ymask |= (unsigned)(v.y & 1) << (4 * i + 1);
        ymask |= (unsigned)(v.z & 1) << (4 * i + 2);
        ymask |= (unsigned)(v.w & 1) << (4 * i + 3);
    }

    // per-row parameters (broadcast loads)
    float d0 = dyn[row * 3 + 0];
    float d1 = dyn[row * 3 + 1];
    float d2 = dyn[row * 3 + 2];
    float ed0 = __expf(d0), ed1 = __expf(d1), ed2 = __expf(d2);
    float rr0 = frcp(1.f + ed0);
    float rr1 = frcp(1.f + ed1);
    float ri2 = frcp(1.f + ed2);
    float t00 = rr0,       t10 = ed0 * rr0;   // src=0 column (sums to 1)
    float t01 = ed1 * rr1, t11 = rr1;         // src=1 column (sums to 1)
    float ai0 = ri2, ai1 = ed2 * ri2;         // normalized alpha_init

    // ---------------- phase 1: emissions + segment 2x2 product ----------------
    float4 A = make_float4(1.f, 0.f, 0.f, 1.f);
#pragma unroll
    for (int j = 0; j < L; j++) {
        int y = (ymask >> j) & 1;
        float e0 = __expf(o[2 * j]), e1 = __expf(o[2 * j + 1]);
        float r0 = frcp(1.f + e0);
        float r1 = frcp(1.f + e1);
        float py0 = y ? e0 * r0 : r0;
        float py1 = y ? r1 : e1 * r1;
        o[2 * j]     = py0;      // keep emissions in registers for phase 3
        o[2 * j + 1] = py1;

        float m00 = t00 * py0, m01 = t01 * py1;
        float m10 = t10 * py0, m11 = t11 * py1;
        // A <- M_j * A
        A = make_float4(m00 * A.x + m01 * A.z,
                        m00 * A.y + m01 * A.w,
                        m10 * A.x + m11 * A.z,
                        m10 * A.y + m11 * A.w);
    }
    int Ea = 0;
    renorm(A, Ea);

    // ---------------- phase 2: Kogge-Stone scans in smem ----------------
    float4 va = A;                                       // -> P_k = A_k ... A_0
    int    ea = Ea;
    float4 vb = make_float4(A.x, A.z, A.y, A.w);         // A^T -> S_k = A_k^T ... A_127^T
    int    eb = Ea;
    sMa[k] = va; sEa[k] = ea;
    sMb[k] = vb; sEb[k] = eb;
    __syncthreads();

#pragma unroll
    for (int d = 1; d < SEG; d <<= 1) {
        float4 na, nb; int nea = 0, neb = 0;
        bool hasA = (k >= d);
        bool hasB = (k + d < SEG);
        if (hasA) { na = sMa[k - d]; nea = sEa[k - d]; }
        if (hasB) { nb = sMb[k + d]; neb = sEb[k + d]; }
        __syncthreads();
        if (hasA) {
            va = mm2(va, na); ea += nea; renorm(va, ea);
            sMa[k] = va; sEa[k] = ea;
        }
        if (hasB) {
            vb = mm2(vb, nb); eb += neb; renorm(vb, eb);
            sMb[k] = vb; sEb[k] = eb;
        }
        __syncthreads();
    }

    // alpha at segment start: P_{k-1} * alpha_init (k=0: alpha_init), C = log scale
    float a0, a1, C;
    if (k == 0) {
        a0 = ai0; a1 = ai1; C = 0.f;
    } else {
        float4 P = sMa[k - 1]; int E = sEa[k - 1];
        float v0 = P.x * ai0 + P.y * ai1;
        float v1 = P.z * ai0 + P.w * ai1;
        float s  = v0 + v1;
        float rs = frcp(s);
        a0 = v0 * rs; a1 = v1 * rs;
        C = __logf(s) + (float)E * LN2F;
    }
    // beta at segment end: row sums of S_{k+1} (k=127: ones); scale irrelevant
    float b0 = 1.f, b1 = 1.f;
    if (k < SEG - 1) {
        float4 U = sMb[k + 1];
        b0 = U.x + U.y;
        b1 = U.z + U.w;
    }

    // ---------------- phase 3: outputs ----------------
    // forward: pred + post + f0
    float f0s[L];
#pragma unroll
    for (int j = 0; j < L; j++) {
        int y = (ymask >> j) & 1;
        float py0 = o[2 * j];
        float py1 = o[2 * j + 1];

        float jj0 = a0 * py0;
        float jj1 = a1 * py1;
        float js  = jj0 + jj1;           // predictive prob of observed symbol
        float ljs = __logf(js);
        float lns = __logf(1.f - js);    // predictive probs sum to 1 (a normalized)
        sP[k * SSTR + 2 * j]     = y ? lns : ljs;
        sP[k * SSTR + 2 * j + 1] = y ? ljs : lns;
        sQ[k * SSTR + 2 * j]     = __logf(jj0) + C;
        sQ[k * SSTR + 2 * j + 1] = __logf(jj1) + C;

        float f  = jj0 * frcp(js);
        f0s[j] = f;
        float fc = 1.f - f;
        a0 = t00 * f + t01 * fc;         // stays normalized (T columns sum to 1)
        a1 = t10 * f + t11 * fc;
        C += ljs;
    }
    // backward: smoothed
#pragma unroll
    for (int j = L - 1; j >= 0; j--) {
        float f  = f0s[j];
        float fc = 1.f - f;
        float g0 = f  * b0;
        float g1 = fc * b1;
        float rg = frcp(g0 + g1);
        sS[k * SSTR + 2 * j]     = __logf(g0 * rg);
        sS[k * SSTR + 2 * j + 1] = __logf(g1 * rg);

        float u0 = o[2 * j]     * b0;
        float u1 = o[2 * j + 1] * b1;
        b0 = t00 * u0 + t10 * u1;        // beta to t-1 (no rescale needed over 8 steps)
        b1 = t01 * u0 + t11 * u1;
    }
    __syncthreads();

    // ---------------- flush: fully-coalesced full-sector stores ----------------
    float* dP = out + (size_t)row * (TT * 2);
    float* dQ = out + (size_t)BN * TT * 2 + (size_t)row * (TT * 2);
    float* dS = out + (size_t)2 * BN * TT * 2 + (size_t)row * (TT * 2);
#pragma unroll
    for (int i = 0; i < 4; i++) {
        int g = i * 512 + k * 4;               // 0..2047, multiple of 4
        int sidx = (g >> 4) * SSTR + (g & 15); // g&15 in {0,4,8,12}: stays in payload
        *(float4*)(dP + g) = make_float4(sP[sidx], sP[sidx + 1], sP[sidx + 2], sP[sidx + 3]);
        *(float4*)(dQ + g) = make_float4(sQ[sidx], sQ[sidx + 1], sQ[sidx + 2], sQ[sidx + 3]);
        *(float4*)(dS + g) = make_float4(sS[sidx], sS[sidx + 1], sS[sidx + 2], sS[sidx + 3]);
    }
}

extern "C" void kernel_launch(void* const* d_in, const int* in_sizes, int n_in,
                              void* d_out, int out_size)
{
    const int*   corr = (const int*)d_in[0];
    const float* dyn  = (const float*)d_in[1];
    const float* obs  = (const float*)d_in[2];
    float* out = (float*)d_out;

    bkt_fused<<<BN, 128>>>(corr, dyn, obs, out);
}

// round 13
// speedup vs baseline: 1.9985x; 1.2031x over previous
#include <cuda_runtime.h>
#include <cstdint>

// BKT 2-state HMM forward-backward, FULLY FUSED: one block = one row.
// Warp-shuffle Kogge-Stone over 128 time segments (L=8 steps each):
//   5 in-warp rounds (shfl) + 1-barrier cross-warp combine via matvecs.
// corr: (B,T) int32 ; dynamics_logits: (B,3) f32 ; obs_logits: (B,T,2) f32
// out: (3,B,T,2) f32 = [output_logprobs, state_posteriors, smoothed]

#define BN   8192
#define TT   1024
#define SEG  128
#define L    8
#define LN2F 0.69314718055994531f
#define SSTR 17   // smem staging stride (16 payload + 1 pad)
#define FULL 0xFFFFFFFFu

__device__ __forceinline__ float frcp(float x) {
    float r;
    asm("rcp.approx.f32 %0, %1;" : "=f"(r) : "f"(x));
    return r;
}

// 2x2 matmul, layout x=m00 y=m01 z=m10 w=m11 ; returns A*B
__device__ __forceinline__ float4 mm2(float4 A, float4 B) {
    return make_float4(A.x * B.x + A.y * B.z,
                       A.x * B.y + A.y * B.w,
                       A.z * B.x + A.w * B.z,
                       A.z * B.y + A.w * B.w);
}

// exact power-of-2 renorm; accumulates exponent
__device__ __forceinline__ void renormE(float4& M, int& E) {
    float s = (M.x + M.y) + (M.z + M.w);
    int eb = (__float_as_int(s) >> 23) & 0xFF;
    float sc = __int_as_float((254 - eb) << 23);
    M.x *= sc; M.y *= sc; M.z *= sc; M.w *= sc;
    E += eb - 127;
}
// renorm, exponent discarded (beta: only ratios matter)
__device__ __forceinline__ void renormD(float4& M) {
    float s = (M.x + M.y) + (M.z + M.w);
    int eb = (__float_as_int(s) >> 23) & 0xFF;
    float sc = __int_as_float((254 - eb) << 23);
    M.x *= sc; M.y *= sc; M.z *= sc; M.w *= sc;
}

__device__ __forceinline__ float4 shflup4(float4 v, int d) {
    return make_float4(__shfl_up_sync(FULL, v.x, d),
                       __shfl_up_sync(FULL, v.y, d),
                       __shfl_up_sync(FULL, v.z, d),
                       __shfl_up_sync(FULL, v.w, d));
}
__device__ __forceinline__ float4 shfldn4(float4 v, int d) {
    return make_float4(__shfl_down_sync(FULL, v.x, d),
                       __shfl_down_sync(FULL, v.y, d),
                       __shfl_down_sync(FULL, v.z, d),
                       __shfl_down_sync(FULL, v.w, d));
}

__global__ __launch_bounds__(128, 6)
void bkt_fused(const int* __restrict__ corr,
               const float* __restrict__ dyn,
               const float* __restrict__ obs,
               float* __restrict__ out)
{
    __shared__ float4 sWa[4];  __shared__ int sEWa[4];  // alpha warp-total matrices
    __shared__ float4 sWb[4];                            // beta warp-total matrices
    __shared__ float sP[128 * SSTR];   // pred staging
    __shared__ float sQ[128 * SSTR];   // post staging
    __shared__ float sS[128 * SSTR];   // smoothed staging

    const int k    = threadIdx.x;      // segment index in row
    const int lane = k & 31;
    const int w    = k >> 5;
    const int row  = blockIdx.x;

    // ---------------- load own segment (contiguous per warp) ----------------
    float o[2 * L];
    const float4* op = (const float4*)(obs + (size_t)row * (TT * 2) + k * (2 * L));
#pragma unroll
    for (int i = 0; i < 4; i++) {
        float4 v = op[i];
        o[4 * i + 0] = v.x; o[4 * i + 1] = v.y;
        o[4 * i + 2] = v.z; o[4 * i + 3] = v.w;
    }
    unsigned ymask = 0;
    const int4* cp = (const int4*)(corr + (size_t)row * TT + k * L);
#pragma unroll
    for (int i = 0; i < 2; i++) {
        int4 v = cp[i];
        ymask |= (unsigned)(v.x & 1) << (4 * i + 0);
        ymask |= (unsigned)(v.y & 1) << (4 * i + 1);
        ymask |= (unsigned)(v.z & 1) << (4 * i + 2);
        ymask |= (unsigned)(v.w & 1) << (4 * i + 3);
    }

    // per-row parameters (broadcast loads)
    float d0 = dyn[row * 3 + 0];
    float d1 = dyn[row * 3 + 1];
    float d2 = dyn[row * 3 + 2];
    float ed0 = __expf(d0), ed1 = __expf(d1), ed2 = __expf(d2);
    float rr0 = frcp(1.f + ed0);
    float rr1 = frcp(1.f + ed1);
    float ri2 = frcp(1.f + ed2);
    float t00 = rr0,       t10 = ed0 * rr0;   // src=0 column (sums to 1)
    float t01 = ed1 * rr1, t11 = rr1;         // src=1 column (sums to 1)
    float ai0 = ri2, ai1 = ed2 * ri2;         // normalized alpha_init

    // ---------------- phase 1: emissions + segment 2x2 product ----------------
    float4 A = make_float4(1.f, 0.f, 0.f, 1.f);
#pragma unroll
    for (int j = 0; j < L; j++) {
        int y = (ymask >> j) & 1;
        float e0 = __expf(o[2 * j]), e1 = __expf(o[2 * j + 1]);
        float r0 = frcp(1.f + e0);
        float r1 = frcp(1.f + e1);
        float py0 = y ? e0 * r0 : r0;
        float py1 = y ? r1 : e1 * r1;
        o[2 * j]     = py0;      // keep emissions in registers
        o[2 * j + 1] = py1;

        float m00 = t00 * py0, m01 = t01 * py1;
        float m10 = t10 * py0, m11 = t11 * py1;
        A = make_float4(m00 * A.x + m01 * A.z,
                        m00 * A.y + m01 * A.w,
                        m10 * A.x + m11 * A.z,
                        m10 * A.y + m11 * A.w);
    }
    int Ea = 0;
    renormE(A, Ea);

    // ---------------- phase 2a: in-warp shuffle scans ----------------
    float4 va = A;  int ea = Ea;                     // prefix: va_k = A_k ... A_first
    float4 vb = make_float4(A.x, A.z, A.y, A.w);     // suffix of A^T: vb_k = A_k^T ... A_last^T
#pragma unroll
    for (int d = 1; d < 32; d <<= 1) {
        float4 na = shflup4(va, d);
        int   nea = __shfl_up_sync(FULL, ea, d);
        float4 nb = shfldn4(vb, d);
        if (lane >= d)      { va = mm2(va, na); ea += nea; renormE(va, ea); }
        if (lane + d < 32)  { vb = mm2(vb, nb); renormD(vb); }
    }
    if (lane == 31) { sWa[w] = va; sEWa[w] = ea; }   // warp-total (alpha)
    if (lane == 0)  { sWb[w] = vb; }                 // warp-total (beta, transposed)
    __syncthreads();

    // ---------------- phase 2b: cross-warp combine via matvecs ----------------
    // alpha vector u = Pre_w * alpha_init,  exponent Eu
    float u0 = ai0, u1 = ai1; int Eu = 0;
#pragma unroll
    for (int i = 0; i < 3; i++) {
        if (i < w) {
            float4 W = sWa[i];
            float n0 = W.x * u0 + W.y * u1;
            float n1 = W.z * u0 + W.w * u1;
            float s  = n0 + n1;
            int eb = (__float_as_int(s) >> 23) & 0xFF;
            float sc = __int_as_float((254 - eb) << 23);
            u0 = n0 * sc; u1 = n1 * sc;
            Eu += sEWa[i] + (eb - 127);
        }
    }
    // beta vector wv = Suf_{w+1} * ones  (scale irrelevant)
    float wv0 = 1.f, wv1 = 1.f;
#pragma unroll
    for (int i = 3; i >= 1; i--) {
        if (i > w) {
            float4 W = sWb[i];
            float n0 = W.x * wv0 + W.y * wv1;
            float n1 = W.z * wv0 + W.w * wv1;
            float rs = frcp(n0 + n1);
            wv0 = n0 * rs; wv1 = n1 * rs;
        }
    }

    // exclusive boundary values via shfl-by-1
    float4 exv = shflup4(va, 1);
    int    exe = __shfl_up_sync(FULL, ea, 1);
    float4 exb = shfldn4(vb, 1);

    float a0, a1, C;
    if (lane == 0) {
        float s  = u0 + u1;
        float rs = frcp(s);
        a0 = u0 * rs; a1 = u1 * rs;
        C = __logf(s) + (float)Eu * LN2F;
    } else {
        float v0 = exv.x * u0 + exv.y * u1;
        float v1 = exv.z * u0 + exv.w * u1;
        float s  = v0 + v1;
        float rs = frcp(s);
        a0 = v0 * rs; a1 = v1 * rs;
        C = __logf(s) + (float)(exe + Eu) * LN2F;
    }
    float b0, b1;
    if (lane == 31) {
        b0 = wv0; b1 = wv1;                           // k=127 -> wv=(1,1) naturally
    } else {
        b0 = exb.x * wv0 + exb.y * wv1;
        b1 = exb.z * wv0 + exb.w * wv1;
    }

    // ---------------- phase 3: outputs ----------------
    float f0s[L];
#pragma unroll
    for (int j = 0; j < L; j++) {
        int y = (ymask >> j) & 1;
        float py0 = o[2 * j];
        float py1 = o[2 * j + 1];

        float jj0 = a0 * py0;
        float jj1 = a1 * py1;
        float js  = jj0 + jj1;           // predictive prob of observed symbol
        float ljs = __logf(js);
        float lns = __logf(1.f - js);    // predictive probs sum to 1 (a normalized)
        sP[k * SSTR + 2 * j]     = y ? lns : ljs;
        sP[k * SSTR + 2 * j + 1] = y ? ljs : lns;
        sQ[k * SSTR + 2 * j]     = __logf(jj0) + C;
        sQ[k * SSTR + 2 * j + 1] = __logf(jj1) + C;

        float f  = jj0 * frcp(js);
        f0s[j] = f;
        float fc = 1.f - f;
        a0 = t00 * f + t01 * fc;         // stays normalized (T columns sum to 1)
        a1 = t10 * f + t11 * fc;
        C += ljs;
    }
#pragma unroll
    for (int j = L - 1; j >= 0; j--) {
        float f  = f0s[j];
        float fc = 1.f - f;
        float g0 = f  * b0;
        float g1 = fc * b1;
        float rg = frcp(g0 + g1);
        sS[k * SSTR + 2 * j]     = __logf(g0 * rg);
        sS[k * SSTR + 2 * j + 1] = __logf(g1 * rg);

        float u0b = o[2 * j]     * b0;
        float u1b = o[2 * j + 1] * b1;
        b0 = t00 * u0b + t10 * u1b;      // beta to t-1 (no rescale needed over 8 steps)
        b1 = t01 * u0b + t11 * u1b;
    }
    __syncthreads();

    // ---------------- flush: fully-coalesced full-sector stores ----------------
    float* dP = out + (size_t)row * (TT * 2);
    float* dQ = out + (size_t)BN * TT * 2 + (size_t)row * (TT * 2);
    float* dS = out + (size_t)2 * BN * TT * 2 + (size_t)row * (TT * 2);
#pragma unroll
    for (int i = 0; i < 4; i++) {
        int g = i * 512 + k * 4;               // 0..2047, multiple of 4
        int sidx = (g >> 4) * SSTR + (g & 15); // g&15 in {0,4,8,12}: stays in payload
        *(float4*)(dP + g) = make_float4(sP[sidx], sP[sidx + 1], sP[sidx + 2], sP[sidx + 3]);
        *(float4*)(dQ + g) = make_float4(sQ[sidx], sQ[sidx + 1], sQ[sidx + 2], sQ[sidx + 3]);
        *(float4*)(dS + g) = make_float4(sS[sidx], sS[sidx + 1], sS[sidx + 2], sS[sidx + 3]);
    }
}

extern "C" void kernel_launch(void* const* d_in, const int* in_sizes, int n_in,
                              void* d_out, int out_size)
{
    const int*   corr = (const int*)d_in[0];
    const float* dyn  = (const float*)d_in[1];
    const float* obs  = (const float*)d_in[2];
    float* out = (float*)d_out;

    bkt_fused<<<BN, 128>>>(corr, dyn, obs, out);
}